// round 2
// baseline (speedup 1.0000x reference)
#include <cuda_runtime.h>
#include <cuda_fp16.h>
#include <stdint.h>

#define CHN   128
#define HWSZ  65536
#define BATCH 4
#define BCHW  33554432ll
#define NWIN  4096
#define TOK   64

// fp16 scratch
__device__ __align__(128) __half g_wh[229376];                    // all weights fp16
__device__ __align__(128) __half g_qkT[4ll * NWIN * TOK * CHN];   // Qopt,Kopt,Qsar,Ksar  [win][tok][ch]
__device__ __align__(128) __half g_vpl[2ll * BCHW];               // Vopt,Vsar planar [b][ch][hw]
__device__ __align__(128) __half g_att[2ll * NWIN * TOK * CHN];   // o2s, s2o  [win][tok][ch]

// ---------------------------------------------------------------------------
__device__ __forceinline__ void mma16816(float c[4],
    uint32_t a0, uint32_t a1, uint32_t a2, uint32_t a3,
    uint32_t b0, uint32_t b1) {
  asm volatile(
    "mma.sync.aligned.m16n8k16.row.col.f32.f16.f16.f32 "
    "{%0,%1,%2,%3}, {%4,%5,%6,%7}, {%8,%9}, {%0,%1,%2,%3};\n"
    : "+f"(c[0]), "+f"(c[1]), "+f"(c[2]), "+f"(c[3])
    : "r"(a0), "r"(a1), "r"(a2), "r"(a3), "r"(b0), "r"(b1));
}
__device__ __forceinline__ uint32_t pack2(float x, float y) {
  __half2 h = __floats2half2_rn(x, y);
  return *reinterpret_cast<uint32_t*>(&h);
}

// ===========================================================================
// K0: weight fp16 conversion
// ===========================================================================
struct PrepArgs { const float* w[11]; };
__global__ __launch_bounds__(256) void k0_prep(PrepArgs a) {
  int i = blockIdx.x * 256 + threadIdx.x;
  if (i >= 229376) return;
  float v;
  if (i < 98304)       v = a.w[i / 16384][i & 16383];
  else if (i < 131072) { int t = i - 98304;  v = a.w[6 + t / 16384][t & 16383]; }
  else                 { int t = i - 131072; v = a.w[8 + t / 32768][t & 32767]; }
  g_wh[i] = __float2half(v);
}

// ===========================================================================
// K1: QKV 1x1 conv.  Block: one image row (256 px) x 128 out-ch, K=128,
// loops over p={Q,K,V}. 256 thr, warp grid 4x2 (M=64,N=64 per warp).
// ===========================================================================
struct K1Args { const float* x[2]; const float* bi[6]; };

__global__ __launch_bounds__(256) void k1_qkv(K1Args a) {
  extern __shared__ char sm[];
  __half* Xs = (__half*)sm;            // [256 px][138]
  __half* Ws = Xs + 256 * 138;         // [128 o ][136]
  int y = blockIdx.x, b = blockIdx.y, z = blockIdx.z;
  int tid = threadIdx.x;
  const float* Xb = a.x[z] + (size_t)b * CHN * HWSZ + (size_t)y * 256;

  for (int j = tid; j < 64 * 256; j += 256) {   // ch-pair x px
    int px = j & 255, cp = j >> 8;
    float v0 = Xb[(size_t)(2 * cp) * HWSZ + px];
    float v1 = Xb[(size_t)(2 * cp + 1) * HWSZ + px];
    *(uint32_t*)&Xs[px * 138 + 2 * cp] = pack2(v0, v1);
  }

  int warp = tid >> 5, lane = tid & 31;
  int g = lane >> 2, tg = lane & 3;
  int wm = warp >> 1, wn = warp & 1;

  for (int p3 = 0; p3 < 3; p3++) {
    int wi = z * 3 + p3;
    __syncthreads();
    const __half* Wg = g_wh + wi * 16384;
    for (int j = tid; j < 2048; j += 256) {
      int o = j >> 4, c8 = (j & 15) * 8;
      *(uint4*)&Ws[o * 136 + c8] = *(const uint4*)&Wg[o * 128 + c8];
    }
    __syncthreads();

    float acc[4][8][4];
#pragma unroll
    for (int mt = 0; mt < 4; mt++)
#pragma unroll
      for (int nt = 0; nt < 8; nt++)
#pragma unroll
        for (int q = 0; q < 4; q++) acc[mt][nt][q] = 0.f;

#pragma unroll
    for (int kk = 0; kk < 8; kk++) {
      int cb = kk * 16 + 2 * tg;
      uint32_t af[4][4], bf[8][2];
#pragma unroll
      for (int mt = 0; mt < 4; mt++) {
        int r = wm * 64 + mt * 16;
        af[mt][0] = *(const uint32_t*)&Xs[(r + g) * 138 + cb];
        af[mt][1] = *(const uint32_t*)&Xs[(r + g + 8) * 138 + cb];
        af[mt][2] = *(const uint32_t*)&Xs[(r + g) * 138 + cb + 8];
        af[mt][3] = *(const uint32_t*)&Xs[(r + g + 8) * 138 + cb + 8];
      }
#pragma unroll
      for (int nt = 0; nt < 8; nt++) {
        int o = wn * 64 + nt * 8 + g;
        bf[nt][0] = *(const uint32_t*)&Ws[o * 136 + cb];
        bf[nt][1] = *(const uint32_t*)&Ws[o * 136 + cb + 8];
      }
#pragma unroll
      for (int mt = 0; mt < 4; mt++)
#pragma unroll
        for (int nt = 0; nt < 8; nt++)
          mma16816(acc[mt][nt], af[mt][0], af[mt][1], af[mt][2], af[mt][3],
                   bf[nt][0], bf[nt][1]);
    }

    const float* Bv = a.bi[wi];
    if (p3 < 2) {  // Q/K -> window-token-major
      __half* outp = g_qkT + (size_t)(z * 2 + p3) * NWIN * TOK * CHN;
      int winrow = b * 1024 + (y >> 3) * 32;
      int tokrow = (y & 7) * 8;
#pragma unroll
      for (int mt = 0; mt < 4; mt++) {
#pragma unroll
        for (int hh = 0; hh < 2; hh++) {
          int px = wm * 64 + mt * 16 + g + hh * 8;
          size_t rbase = ((size_t)(winrow + (px >> 3)) * 64 + tokrow + (px & 7)) * 128;
#pragma unroll
          for (int nt = 0; nt < 8; nt++) {
            int o = wn * 64 + nt * 8 + 2 * tg;
            *(uint32_t*)&outp[rbase + o] =
                pack2(acc[mt][nt][hh * 2] + Bv[o], acc[mt][nt][hh * 2 + 1] + Bv[o + 1]);
          }
        }
      }
    } else {  // V -> planar
      __half* outp = g_vpl + (size_t)z * BCHW + (size_t)b * CHN * HWSZ + (size_t)y * 256;
#pragma unroll
      for (int nt = 0; nt < 8; nt++) {
        int o = wn * 64 + nt * 8 + 2 * tg;
        float b0 = Bv[o], b1 = Bv[o + 1];
#pragma unroll
        for (int mt = 0; mt < 4; mt++) {
          int px = wm * 64 + mt * 16 + g;
          outp[(size_t)o * HWSZ + px]           = __float2half(acc[mt][nt][0] + b0);
          outp[(size_t)(o + 1) * HWSZ + px]     = __float2half(acc[mt][nt][1] + b1);
          outp[(size_t)o * HWSZ + px + 8]       = __float2half(acc[mt][nt][2] + b0);
          outp[(size_t)(o + 1) * HWSZ + px + 8] = __float2half(acc[mt][nt][3] + b1);
        }
      }
    }
  }
}

// ===========================================================================
// K2: window cross-attention + projection. One block per (window, dir).
// 128 thr = 4 warps, one warp per head in attention, 16 token-rows each in proj.
// ===========================================================================
struct K2Args { const float* pb[2]; };

__global__ __launch_bounds__(128) void k2_attn(K2Args a) {
  extern __shared__ char sm[];
  __half* qs = (__half*)sm;        // [64 tok][136]
  __half* ks = qs + 64 * 136;      // [64 tok][136]
  __half* vs = ks + 64 * 136;      // [128 ch][72]
  __half* os = vs + 128 * 72;      // [64 tok][136]
  __half* ws = os + 64 * 136;      // [128 o ][136]

  int win = blockIdx.x, d = blockIdx.y;
  int b = win >> 10, wy = (win >> 5) & 31, wx = win & 31;
  int wpos = wy * 2048 + wx * 8;
  int qslot = d == 0 ? 0 : 2;
  int kslot = d == 0 ? 3 : 1;
  int vz = d == 0 ? 1 : 0;
  int tid = threadIdx.x;

  const __half* Qg = g_qkT + ((size_t)qslot * NWIN + win) * TOK * CHN;
  const __half* Kg = g_qkT + ((size_t)kslot * NWIN + win) * TOK * CHN;
  const __half* Vg = g_vpl + (size_t)vz * BCHW + (size_t)b * CHN * HWSZ;

  for (int j = tid; j < 1024; j += 128) {
    int tok = j >> 4, c8 = (j & 15) * 8;
    *(uint4*)&qs[tok * 136 + c8] = *(const uint4*)&Qg[tok * 128 + c8];
    *(uint4*)&ks[tok * 136 + c8] = *(const uint4*)&Kg[tok * 128 + c8];
  }
  for (int j = tid; j < 1024; j += 128) {
    int ch = j >> 3, rb = j & 7;
    *(uint4*)&vs[ch * 72 + rb * 8] =
        *(const uint4*)&Vg[(size_t)ch * HWSZ + wpos + rb * 256];
  }
  const __half* Pw = g_wh + 98304 + d * 16384;
  for (int j = tid; j < 2048; j += 128) {
    int o = j >> 4, c8 = (j & 15) * 8;
    *(uint4*)&ws[o * 136 + c8] = *(const uint4*)&Pw[o * 128 + c8];
  }
  __syncthreads();

  int h = tid >> 5, lane = tid & 31;
  int g = lane >> 2, tg = lane & 3;
  const float scale = 0.1767766952966369f;

  for (int cq = 0; cq < 4; cq++) {
    int qr = cq * 16;
    float sc[8][4];
#pragma unroll
    for (int nt = 0; nt < 8; nt++)
#pragma unroll
      for (int q = 0; q < 4; q++) sc[nt][q] = 0.f;

#pragma unroll
    for (int kk = 0; kk < 2; kk++) {
      int cb = h * 32 + kk * 16 + 2 * tg;
      uint32_t a0 = *(const uint32_t*)&qs[(qr + g) * 136 + cb];
      uint32_t a1 = *(const uint32_t*)&qs[(qr + g + 8) * 136 + cb];
      uint32_t a2 = *(const uint32_t*)&qs[(qr + g) * 136 + cb + 8];
      uint32_t a3 = *(const uint32_t*)&qs[(qr + g + 8) * 136 + cb + 8];
#pragma unroll
      for (int nt = 0; nt < 8; nt++) {
        uint32_t b0 = *(const uint32_t*)&ks[(nt * 8 + g) * 136 + cb];
        uint32_t b1 = *(const uint32_t*)&ks[(nt * 8 + g) * 136 + cb + 8];
        mma16816(sc[nt], a0, a1, a2, a3, b0, b1);
      }
    }

    float m0 = -1e30f, m1 = -1e30f;
#pragma unroll
    for (int nt = 0; nt < 8; nt++) {
      m0 = fmaxf(m0, fmaxf(sc[nt][0], sc[nt][1]));
      m1 = fmaxf(m1, fmaxf(sc[nt][2], sc[nt][3]));
    }
#pragma unroll
    for (int o = 1; o < 4; o <<= 1) {
      m0 = fmaxf(m0, __shfl_xor_sync(0xffffffffu, m0, o));
      m1 = fmaxf(m1, __shfl_xor_sync(0xffffffffu, m1, o));
    }
    float l0 = 0.f, l1 = 0.f;
#pragma unroll
    for (int nt = 0; nt < 8; nt++) {
      sc[nt][0] = __expf(scale * (sc[nt][0] - m0));
      sc[nt][1] = __expf(scale * (sc[nt][1] - m0));
      sc[nt][2] = __expf(scale * (sc[nt][2] - m1));
      sc[nt][3] = __expf(scale * (sc[nt][3] - m1));
      l0 += sc[nt][0] + sc[nt][1];
      l1 += sc[nt][2] + sc[nt][3];
    }
#pragma unroll
    for (int o = 1; o < 4; o <<= 1) {
      l0 += __shfl_xor_sync(0xffffffffu, l0, o);
      l1 += __shfl_xor_sync(0xffffffffu, l1, o);
    }
    float r0 = 1.f / l0, r1 = 1.f / l1;

    float oacc[4][4];
#pragma unroll
    for (int nv = 0; nv < 4; nv++)
#pragma unroll
      for (int q = 0; q < 4; q++) oacc[nv][q] = 0.f;
#pragma unroll
    for (int kt = 0; kt < 4; kt++) {
      uint32_t a0 = pack2(sc[2 * kt][0] * r0, sc[2 * kt][1] * r0);
      uint32_t a1 = pack2(sc[2 * kt][2] * r1, sc[2 * kt][3] * r1);
      uint32_t a2 = pack2(sc[2 * kt + 1][0] * r0, sc[2 * kt + 1][1] * r0);
      uint32_t a3 = pack2(sc[2 * kt + 1][2] * r1, sc[2 * kt + 1][3] * r1);
#pragma unroll
      for (int nv = 0; nv < 4; nv++) {
        int ch = h * 32 + nv * 8 + g;
        uint32_t b0 = *(const uint32_t*)&vs[ch * 72 + kt * 16 + 2 * tg];
        uint32_t b1 = *(const uint32_t*)&vs[ch * 72 + kt * 16 + 2 * tg + 8];
        mma16816(oacc[nv], a0, a1, a2, a3, b0, b1);
      }
    }
#pragma unroll
    for (int nv = 0; nv < 4; nv++) {
      int cc = h * 32 + nv * 8 + 2 * tg;
      *(uint32_t*)&os[(qr + g) * 136 + cc] = pack2(oacc[nv][0], oacc[nv][1]);
      *(uint32_t*)&os[(qr + g + 8) * 136 + cc] = pack2(oacc[nv][2], oacc[nv][3]);
    }
  }
  __syncthreads();

  // projection GEMM: [64 tok] x [128 out], K=128
  float pacc[16][4];
#pragma unroll
  for (int nt = 0; nt < 16; nt++)
#pragma unroll
    for (int q = 0; q < 4; q++) pacc[nt][q] = 0.f;
#pragma unroll
  for (int kt = 0; kt < 8; kt++) {
    int cb = kt * 16 + 2 * tg;
    uint32_t a0 = *(const uint32_t*)&os[(h * 16 + g) * 136 + cb];
    uint32_t a1 = *(const uint32_t*)&os[(h * 16 + g + 8) * 136 + cb];
    uint32_t a2 = *(const uint32_t*)&os[(h * 16 + g) * 136 + cb + 8];
    uint32_t a3 = *(const uint32_t*)&os[(h * 16 + g + 8) * 136 + cb + 8];
#pragma unroll
    for (int nt = 0; nt < 16; nt++) {
      uint32_t b0 = *(const uint32_t*)&ws[(nt * 8 + g) * 136 + cb];
      uint32_t b1 = *(const uint32_t*)&ws[(nt * 8 + g) * 136 + cb + 8];
      mma16816(pacc[nt], a0, a1, a2, a3, b0, b1);
    }
  }
  const float* PB = a.pb[d];
  __half* outp = g_att + ((size_t)d * NWIN + win) * (TOK * CHN);
#pragma unroll
  for (int nt = 0; nt < 16; nt++) {
    int o = nt * 8 + 2 * tg;
    float bb0 = PB[o], bb1 = PB[o + 1];
    *(uint32_t*)&outp[(h * 16 + g) * 128 + o] =
        pack2(pacc[nt][0] + bb0, pacc[nt][1] + bb1);
    *(uint32_t*)&outp[(h * 16 + g + 8) * 128 + o] =
        pack2(pacc[nt][2] + bb0, pacc[nt][3] + bb1);
  }
}

// ===========================================================================
// K3: gates + residual + fuse + BN + SiLU. One block per window, 256 thr.
// ===========================================================================
struct K3Args {
  const float *fo, *fs;
  const float *gob, *gsb, *fb;
  const float *gamma, *beta, *mean, *var;
  float* out;
};

__global__ __launch_bounds__(256) void k3_fuse(K3Args a) {
  extern __shared__ char sm[];
  __half* ao = (__half*)sm;           // [64 tok][264]  (opt | o2s -> opt_new|sar_new)
  __half* as_ = ao + 64 * 264;        // [64 tok][264]  (sar | s2o)
  __half* wsm = as_ + 64 * 264;       // [128 o][264]
  float* sigst = (float*)(sm + 135168);  // [2][128 ch][68 tok]

  int win = blockIdx.x;
  int b = win >> 10, wy = (win >> 5) & 31, wx = win & 31;
  int wpos = wy * 2048 + wx * 8;
  int tid = threadIdx.x;

  for (int j = tid; j < 64 * 64; j += 256) {   // ch-pair x tok
    int n = j & 63, cp = j >> 6;
    int pos = wpos + (n >> 3) * 256 + (n & 7);
    size_t gi = (size_t)b * CHN * HWSZ + pos;
    float o0 = a.fo[gi + (size_t)(2 * cp) * HWSZ];
    float o1 = a.fo[gi + (size_t)(2 * cp + 1) * HWSZ];
    *(uint32_t*)&ao[n * 264 + 2 * cp] = pack2(o0, o1);
    float s0 = a.fs[gi + (size_t)(2 * cp) * HWSZ];
    float s1 = a.fs[gi + (size_t)(2 * cp + 1) * HWSZ];
    *(uint32_t*)&as_[n * 264 + 2 * cp] = pack2(s0, s1);
  }
  {
    const __half* A0 = g_att + (size_t)win * TOK * CHN;
    const __half* A1 = g_att + ((size_t)NWIN + win) * TOK * CHN;
    for (int j = tid; j < 1024; j += 256) {
      int tok = j >> 4, c8 = (j & 15) * 8;
      *(uint4*)&ao[tok * 264 + 128 + c8] = *(const uint4*)&A0[tok * 128 + c8];
      *(uint4*)&as_[tok * 264 + 128 + c8] = *(const uint4*)&A1[tok * 128 + c8];
    }
  }

  int warp = tid >> 5, lane = tid & 31;
  int g = lane >> 2, tg = lane & 3;
  int wm = warp >> 2, wn = warp & 3;       // 2x4 -> wm 0..1? need 4x2:
  wm = warp >> 1; wn = warp & 1;           // warp tile: 16 tok x 64 out

  float sgo[8][4], sgs[8][4];

  // --- gate opt ---
  __syncthreads();
  for (int j = tid; j < 4096; j += 256) {
    int o = j >> 5, c8 = (j & 31) * 8;
    *(uint4*)&wsm[o * 264 + c8] = *(const uint4*)&g_wh[131072 + o * 256 + c8];
  }
  __syncthreads();
#pragma unroll
  for (int nt = 0; nt < 8; nt++)
#pragma unroll
    for (int q = 0; q < 4; q++) sgo[nt][q] = 0.f;
#pragma unroll
  for (int kt = 0; kt < 16; kt++) {
    int cb = kt * 16 + 2 * tg;
    uint32_t a0 = *(const uint32_t*)&ao[(wm * 16 + g) * 264 + cb];
    uint32_t a1 = *(const uint32_t*)&ao[(wm * 16 + g + 8) * 264 + cb];
    uint32_t a2 = *(const uint32_t*)&ao[(wm * 16 + g) * 264 + cb + 8];
    uint32_t a3 = *(const uint32_t*)&ao[(wm * 16 + g + 8) * 264 + cb + 8];
#pragma unroll
    for (int nt = 0; nt < 8; nt++) {
      uint32_t b0 = *(const uint32_t*)&wsm[(wn * 64 + nt * 8 + g) * 264 + cb];
      uint32_t b1 = *(const uint32_t*)&wsm[(wn * 64 + nt * 8 + g) * 264 + cb + 8];
      mma16816(sgo[nt], a0, a1, a2, a3, b0, b1);
    }
  }
#pragma unroll
  for (int nt = 0; nt < 8; nt++) {
    int o = wn * 64 + nt * 8 + 2 * tg;
    sgo[nt][0] = 1.f / (1.f + __expf(-(sgo[nt][0] + a.gob[o])));
    sgo[nt][1] = 1.f / (1.f + __expf(-(sgo[nt][1] + a.gob[o + 1])));
    sgo[nt][2] = 1.f / (1.f + __expf(-(sgo[nt][2] + a.gob[o])));
    sgo[nt][3] = 1.f / (1.f + __expf(-(sgo[nt][3] + a.gob[o + 1])));
  }

  // --- gate sar ---
  __syncthreads();
  for (int j = tid; j < 4096; j += 256) {
    int o = j >> 5, c8 = (j & 31) * 8;
    *(uint4*)&wsm[o * 264 + c8] = *(const uint4*)&g_wh[163840 + o * 256 + c8];
  }
  __syncthreads();
#pragma unroll
  for (int nt = 0; nt < 8; nt++)
#pragma unroll
    for (int q = 0; q < 4; q++) sgs[nt][q] = 0.f;
#pragma unroll
  for (int kt = 0; kt < 16; kt++) {
    int cb = kt * 16 + 2 * tg;
    uint32_t a0 = *(const uint32_t*)&as_[(wm * 16 + g) * 264 + cb];
    uint32_t a1 = *(const uint32_t*)&as_[(wm * 16 + g + 8) * 264 + cb];
    uint32_t a2 = *(const uint32_t*)&as_[(wm * 16 + g) * 264 + cb + 8];
    uint32_t a3 = *(const uint32_t*)&as_[(wm * 16 + g + 8) * 264 + cb + 8];
#pragma unroll
    for (int nt = 0; nt < 8; nt++) {
      uint32_t b0 = *(const uint32_t*)&wsm[(wn * 64 + nt * 8 + g) * 264 + cb];
      uint32_t b1 = *(const uint32_t*)&wsm[(wn * 64 + nt * 8 + g) * 264 + cb + 8];
      mma16816(sgs[nt], a0, a1, a2, a3, b0, b1);
    }
  }
#pragma unroll
  for (int nt = 0; nt < 8; nt++) {
    int o = wn * 64 + nt * 8 + 2 * tg;
    int t0 = wm * 16 + g;
    sgs[nt][0] = 1.f / (1.f + __expf(-(sgs[nt][0] + a.gsb[o])));
    sgs[nt][1] = 1.f / (1.f + __expf(-(sgs[nt][1] + a.gsb[o + 1])));
    sgs[nt][2] = 1.f / (1.f + __expf(-(sgs[nt][2] + a.gsb[o])));
    sgs[nt][3] = 1.f / (1.f + __expf(-(sgs[nt][3] + a.gsb[o + 1])));
    // stage sigmas [ch][tok]
    sigst[o * 68 + t0] = sgo[nt][0];
    sigst[(o + 1) * 68 + t0] = sgo[nt][1];
    sigst[o * 68 + t0 + 8] = sgo[nt][2];
    sigst[(o + 1) * 68 + t0 + 8] = sgo[nt][3];
    sigst[8704 + o * 68 + t0] = sgs[nt][0];
    sigst[8704 + (o + 1) * 68 + t0] = sgs[nt][1];
    sigst[8704 + o * 68 + t0 + 8] = sgs[nt][2];
    sigst[8704 + (o + 1) * 68 + t0 + 8] = sgs[nt][3];
  }
  __syncthreads();

  // residual update in smem + coalesced sigma writes
  for (int j = tid; j < 8192; j += 256) {
    int n = j & 63, c = j >> 6;
    int pos = wpos + (n >> 3) * 256 + (n & 7);
    size_t gi = (size_t)b * CHN * HWSZ + (size_t)c * HWSZ + pos;
    float so = sigst[c * 68 + n], ss = sigst[8704 + c * 68 + n];
    float fo = __half2float(ao[n * 264 + c]);
    float f2 = __half2float(ao[n * 264 + 128 + c]);
    float fs = __half2float(as_[n * 264 + c]);
    float f3 = __half2float(as_[n * 264 + 128 + c]);
    ao[n * 264 + c] = __float2half(fo + so * f2);
    ao[n * 264 + 128 + c] = __float2half(fs + ss * f3);
    a.out[BCHW + gi] = so;
    a.out[2 * BCHW + gi] = ss;
  }
  __syncthreads();
  for (int j = tid; j < 4096; j += 256) {
    int o = j >> 5, c8 = (j & 31) * 8;
    *(uint4*)&wsm[o * 264 + c8] = *(const uint4*)&g_wh[196608 + o * 256 + c8];
  }
  __syncthreads();

  // fuse GEMM
  float facc[8][4];
#pragma unroll
  for (int nt = 0; nt < 8; nt++)
#pragma unroll
    for (int q = 0; q < 4; q++) facc[nt][q] = 0.f;
#pragma unroll
  for (int kt = 0; kt < 16; kt++) {
    int cb = kt * 16 + 2 * tg;
    uint32_t a0 = *(const uint32_t*)&ao[(wm * 16 + g) * 264 + cb];
    uint32_t a1 = *(const uint32_t*)&ao[(wm * 16 + g + 8) * 264 + cb];
    uint32_t a2 = *(const uint32_t*)&ao[(wm * 16 + g) * 264 + cb + 8];
    uint32_t a3 = *(const uint32_t*)&ao[(wm * 16 + g + 8) * 264 + cb + 8];
#pragma unroll
    for (int nt = 0; nt < 8; nt++) {
      uint32_t b0 = *(const uint32_t*)&wsm[(wn * 64 + nt * 8 + g) * 264 + cb];
      uint32_t b1 = *(const uint32_t*)&wsm[(wn * 64 + nt * 8 + g) * 264 + cb + 8];
      mma16816(facc[nt], a0, a1, a2, a3, b0, b1);
    }
  }
#pragma unroll
  for (int nt = 0; nt < 8; nt++) {
    int o = wn * 64 + nt * 8 + 2 * tg;
    int t0 = wm * 16 + g;
    sigst[o * 68 + t0] = facc[nt][0];
    sigst[(o + 1) * 68 + t0] = facc[nt][1];
    sigst[o * 68 + t0 + 8] = facc[nt][2];
    sigst[(o + 1) * 68 + t0 + 8] = facc[nt][3];
  }
  __syncthreads();

  for (int j = tid; j < 8192; j += 256) {
    int n = j & 63, c = j >> 6;
    int pos = wpos + (n >> 3) * 256 + (n & 7);
    size_t gi = (size_t)b * CHN * HWSZ + (size_t)c * HWSZ + pos;
    float v = sigst[c * 68 + n] + a.fb[c];
    float inv = a.gamma[c] * rsqrtf(a.var[c] + 1e-5f);
    float f = v * inv + (a.beta[c] - a.mean[c] * inv);
    a.out[gi] = f / (1.f + __expf(-f));
  }
}

// ===========================================================================
extern "C" void kernel_launch(void* const* d_in, const int* in_sizes, int n_in,
                              void* d_out, int out_size) {
  const float* F_opt = (const float*)d_in[0];
  const float* F_sar = (const float*)d_in[1];

  cudaFuncSetAttribute(k1_qkv, cudaFuncAttributeMaxDynamicSharedMemorySize, 105472);
  cudaFuncSetAttribute(k2_attn, cudaFuncAttributeMaxDynamicSharedMemorySize, 105472);
  cudaFuncSetAttribute(k3_fuse, cudaFuncAttributeMaxDynamicSharedMemorySize, 204800);

  PrepArgs pa;
  pa.w[0] = (const float*)d_in[2];   // wq_opt
  pa.w[1] = (const float*)d_in[4];   // wk_opt
  pa.w[2] = (const float*)d_in[6];   // wv_opt
  pa.w[3] = (const float*)d_in[8];   // wq_sar
  pa.w[4] = (const float*)d_in[10];  // wk_sar
  pa.w[5] = (const float*)d_in[12];  // wv_sar
  pa.w[6] = (const float*)d_in[14];  // proj_w_o2s
  pa.w[7] = (const float*)d_in[16];  // proj_w_s2o
  pa.w[8] = (const float*)d_in[18];  // gate_opt_w
  pa.w[9] = (const float*)d_in[20];  // gate_sar_w
  pa.w[10] = (const float*)d_in[22]; // fuse_w
  k0_prep<<<896, 256>>>(pa);

  K1Args a1;
  a1.x[0] = F_opt; a1.x[1] = F_sar;
  a1.bi[0] = (const float*)d_in[3];
  a1.bi[1] = (const float*)d_in[5];
  a1.bi[2] = (const float*)d_in[7];
  a1.bi[3] = (const float*)d_in[9];
  a1.bi[4] = (const float*)d_in[11];
  a1.bi[5] = (const float*)d_in[13];
  k1_qkv<<<dim3(256, 4, 2), 256, 105472>>>(a1);

  K2Args a2;
  a2.pb[0] = (const float*)d_in[15];
  a2.pb[1] = (const float*)d_in[17];
  k2_attn<<<dim3(4096, 2), 128, 105472>>>(a2);

  K3Args a3;
  a3.fo = F_opt; a3.fs = F_sar;
  a3.gob = (const float*)d_in[19];
  a3.gsb = (const float*)d_in[21];
  a3.fb = (const float*)d_in[23];
  a3.gamma = (const float*)d_in[24];
  a3.beta = (const float*)d_in[25];
  a3.mean = (const float*)d_in[26];
  a3.var = (const float*)d_in[27];
  a3.out = (float*)d_out;
  k3_fuse<<<4096, 256, 204800>>>(a3);
}

// round 6
// speedup vs baseline: 1.8101x; 1.8101x over previous
#include <cuda_runtime.h>
#include <cuda_fp16.h>
#include <stdint.h>

#define CHN   128
#define HWSZ  65536
#define BATCH 4
#define BCHW  33554432ll
#define NWIN  4096
#define TOK   64

// fp16 scratch buffers
__device__ __align__(128) __half g_wh[229376];            // all weights fp16
__device__ __align__(128) __half g_qkT[4ll * BCHW];       // Qopt,Kopt,Qsar,Ksar [win][tok][ch] (Q pre-scaled)
__device__ __align__(128) __half g_vwin[2ll * BCHW];      // Vopt,Vsar [win][ch][tok]
__device__ __align__(128) __half g_attn[2ll * BCHW];      // pre-proj attn out [d][win][tok][ch]
__device__ __align__(128) __half g_attp[2ll * BCHW];      // post-proj NHWC [d][b][hw][ch]
__device__ __align__(128) __half g_Fh[2ll * BCHW];        // F_opt,F_sar fp16 NHWC
__device__ __align__(128) __half g_new[2ll * BCHW];       // opt_new,sar_new NHWC

// ---------------------------------------------------------------------------
__device__ __forceinline__ void mma16816(float c[4],
    uint32_t a0, uint32_t a1, uint32_t a2, uint32_t a3,
    uint32_t b0, uint32_t b1) {
  asm volatile(
    "mma.sync.aligned.m16n8k16.row.col.f32.f16.f16.f32 "
    "{%0,%1,%2,%3}, {%4,%5,%6,%7}, {%8,%9}, {%0,%1,%2,%3};\n"
    : "+f"(c[0]), "+f"(c[1]), "+f"(c[2]), "+f"(c[3])
    : "r"(a0), "r"(a1), "r"(a2), "r"(a3), "r"(b0), "r"(b1));
}
__device__ __forceinline__ uint32_t pack2(float x, float y) {
  __half2 h = __floats2half2_rn(x, y);
  return *reinterpret_cast<uint32_t*>(&h);
}

// ===========================================================================
// K0: weight fp16 conversion
// ===========================================================================
struct PrepArgs { const float* w[11]; };
__global__ __launch_bounds__(256) void k0_prep(PrepArgs a) {
  int i = blockIdx.x * 256 + threadIdx.x;
  if (i >= 229376) return;
  float v;
  if (i < 98304)       v = a.w[i / 16384][i & 16383];
  else if (i < 131072) { int t = i - 98304;  v = a.w[6 + t / 16384][t & 16383]; }
  else                 { int t = i - 131072; v = a.w[8 + t / 32768][t & 32767]; }
  g_wh[i] = __float2half(v);
}

// ===========================================================================
// K1: QKV 1x1 conv, tile 128px x 128out, K=128. Also emits F fp16 NHWC.
// 256 thr, 8 warps (wm 0..3: 32px, wn 0..1: 64ch).
// ===========================================================================
struct K1Args { const float* x[2]; const float* bi[6]; };

__global__ __launch_bounds__(256, 2) void k1_qkv(K1Args a) {
  extern __shared__ char sm[];
  __half* Xs = (__half*)sm;         // [128][136]
  __half* Ws = Xs + 128 * 136;      // [128][136], reused as output stage

  int tile = blockIdx.x, z = blockIdx.y;
  int p0 = tile * 128;
  int b = p0 >> 16;
  int hw0 = p0 & 65535;
  int y = hw0 >> 8, x0 = hw0 & 255;
  int tid = threadIdx.x;
  const float* Xb = a.x[z] + (size_t)b * CHN * HWSZ + hw0;

  for (int j = tid; j < 64 * 128; j += 256) {
    int px = j & 127, cp = j >> 7;
    float v0 = Xb[(size_t)(2 * cp) * HWSZ + px];
    float v1 = Xb[(size_t)(2 * cp + 1) * HWSZ + px];
    *(uint32_t*)&Xs[px * 136 + 2 * cp] = pack2(v0, v1);
  }
  __syncthreads();

  // F fp16 NHWC
  {
    __half* fo = g_Fh + (size_t)z * BCHW + ((size_t)b * HWSZ + hw0) * 128;
    for (int j = tid; j < 2048; j += 256) {
      int px = j >> 4, c8 = (j & 15) * 8;
      *(uint4*)&fo[(size_t)px * 128 + c8] = *(const uint4*)&Xs[px * 136 + c8];
    }
  }

  int warp = tid >> 5, lane = tid & 31;
  int g = lane >> 2, tg = lane & 3;
  int wm = warp >> 1, wn = warp & 1;

  for (int p3 = 0; p3 < 3; p3++) {
    int wi = z * 3 + p3;
    __syncthreads();
    const __half* Wg = g_wh + wi * 16384;
    for (int j = tid; j < 2048; j += 256) {
      int o = j >> 4, c8 = (j & 15) * 8;
      *(uint4*)&Ws[o * 136 + c8] = *(const uint4*)&Wg[o * 128 + c8];
    }
    __syncthreads();

    float acc[2][8][4];
#pragma unroll
    for (int mt = 0; mt < 2; mt++)
#pragma unroll
      for (int nt = 0; nt < 8; nt++)
#pragma unroll
        for (int q = 0; q < 4; q++) acc[mt][nt][q] = 0.f;

#pragma unroll
    for (int kk = 0; kk < 8; kk++) {
      int cb = kk * 16 + 2 * tg;
      uint32_t af[2][4], bf[8][2];
#pragma unroll
      for (int mt = 0; mt < 2; mt++) {
        int r = wm * 32 + mt * 16;
        af[mt][0] = *(const uint32_t*)&Xs[(r + g) * 136 + cb];
        af[mt][1] = *(const uint32_t*)&Xs[(r + g + 8) * 136 + cb];
        af[mt][2] = *(const uint32_t*)&Xs[(r + g) * 136 + cb + 8];
        af[mt][3] = *(const uint32_t*)&Xs[(r + g + 8) * 136 + cb + 8];
      }
#pragma unroll
      for (int nt = 0; nt < 8; nt++) {
        int o = wn * 64 + nt * 8 + g;
        bf[nt][0] = *(const uint32_t*)&Ws[o * 136 + cb];
        bf[nt][1] = *(const uint32_t*)&Ws[o * 136 + cb + 8];
      }
#pragma unroll
      for (int mt = 0; mt < 2; mt++)
#pragma unroll
        for (int nt = 0; nt < 8; nt++)
          mma16816(acc[mt][nt], af[mt][0], af[mt][1], af[mt][2], af[mt][3],
                   bf[nt][0], bf[nt][1]);
    }
    __syncthreads();  // weights consumed; Ws becomes output stage

    const float* Bv = a.bi[wi];
    float qs_ = (p3 == 0) ? 0.1767766952966369f : 1.0f;  // fold softmax scale into Q

    if (p3 < 2) {  // Q/K -> stage [px][ch] -> window-token-major
#pragma unroll
      for (int mt = 0; mt < 2; mt++) {
        int px = wm * 32 + mt * 16 + g;
#pragma unroll
        for (int nt = 0; nt < 8; nt++) {
          int o = wn * 64 + nt * 8 + 2 * tg;
          *(uint32_t*)&Ws[px * 136 + o] =
              pack2((acc[mt][nt][0] + Bv[o]) * qs_, (acc[mt][nt][1] + Bv[o + 1]) * qs_);
          *(uint32_t*)&Ws[(px + 8) * 136 + o] =
              pack2((acc[mt][nt][2] + Bv[o]) * qs_, (acc[mt][nt][3] + Bv[o + 1]) * qs_);
        }
      }
      __syncthreads();
      __half* outp = g_qkT + (size_t)(z * 2 + p3) * BCHW;
      for (int j = tid; j < 2048; j += 256) {
        int px = j >> 4, c8 = (j & 15) * 8;
        int x = x0 + px;
        int win = b * 1024 + (y >> 3) * 32 + (x >> 3);
        int tok = (y & 7) * 8 + (x & 7);
        *(uint4*)&outp[((size_t)win * 64 + tok) * 128 + c8] =
            *(const uint4*)&Ws[px * 136 + c8];
      }
    } else {  // V -> stage [ch][px] -> [win][ch][tok]
#pragma unroll
      for (int mt = 0; mt < 2; mt++) {
        int px = wm * 32 + mt * 16 + g;
#pragma unroll
        for (int nt = 0; nt < 8; nt++) {
          int o = wn * 64 + nt * 8 + 2 * tg;
          Ws[o * 136 + px] = __float2half(acc[mt][nt][0] + Bv[o]);
          Ws[(o + 1) * 136 + px] = __float2half(acc[mt][nt][1] + Bv[o + 1]);
          Ws[o * 136 + px + 8] = __float2half(acc[mt][nt][2] + Bv[o]);
          Ws[(o + 1) * 136 + px + 8] = __float2half(acc[mt][nt][3] + Bv[o + 1]);
        }
      }
      __syncthreads();
      __half* outp = g_vwin + (size_t)z * BCHW;
      for (int j = tid; j < 2048; j += 256) {
        int ch = j >> 4, px8 = (j & 15) * 8;
        int x = x0 + px8;
        int win = b * 1024 + (y >> 3) * 32 + (x >> 3);
        int tokb = (y & 7) * 8;
        *(uint4*)&outp[((size_t)win * 128 + ch) * 64 + tokb] =
            *(const uint4*)&Ws[ch * 136 + px8];
      }
    }
  }
}

// ===========================================================================
// K2: window cross-attention (no proj). One block per (window, dir), 128 thr.
// ===========================================================================
__global__ __launch_bounds__(128, 3) void k2_attn() {
  extern __shared__ char sm[];
  __half* qs = (__half*)sm;        // [64][136]
  __half* ks = qs + 64 * 136;      // [64][136]
  __half* vs = ks + 64 * 136;      // [128][72]
  __half* os = vs + 128 * 72;      // [64][136]

  int win = blockIdx.x, d = blockIdx.y;
  int qslot = d == 0 ? 0 : 2;
  int kslot = d == 0 ? 3 : 1;
  int vz = d == 0 ? 1 : 0;
  int tid = threadIdx.x;

  const __half* Qg = g_qkT + ((size_t)qslot * NWIN + win) * TOK * CHN;
  const __half* Kg = g_qkT + ((size_t)kslot * NWIN + win) * TOK * CHN;
  const __half* Vg = g_vwin + (size_t)vz * BCHW + (size_t)win * CHN * TOK;

  for (int j = tid; j < 1024; j += 128) {
    int tok = j >> 4, c8 = (j & 15) * 8;
    *(uint4*)&qs[tok * 136 + c8] = *(const uint4*)&Qg[tok * 128 + c8];
    *(uint4*)&ks[tok * 136 + c8] = *(const uint4*)&Kg[tok * 128 + c8];
  }
  for (int j = tid; j < 1024; j += 128) {
    int ch = j >> 3, t8 = (j & 7) * 8;
    *(uint4*)&vs[ch * 72 + t8] = *(const uint4*)&Vg[ch * 64 + t8];
  }
  __syncthreads();

  int h = tid >> 5, lane = tid & 31;
  int g = lane >> 2, tg = lane & 3;

  for (int cq = 0; cq < 4; cq++) {
    int qr = cq * 16;
    float sc[8][4];
#pragma unroll
    for (int nt = 0; nt < 8; nt++)
#pragma unroll
      for (int q = 0; q < 4; q++) sc[nt][q] = 0.f;

#pragma unroll
    for (int kk = 0; kk < 2; kk++) {
      int cb = h * 32 + kk * 16 + 2 * tg;
      uint32_t a0 = *(const uint32_t*)&qs[(qr + g) * 136 + cb];
      uint32_t a1 = *(const uint32_t*)&qs[(qr + g + 8) * 136 + cb];
      uint32_t a2 = *(const uint32_t*)&qs[(qr + g) * 136 + cb + 8];
      uint32_t a3 = *(const uint32_t*)&qs[(qr + g + 8) * 136 + cb + 8];
#pragma unroll
      for (int nt = 0; nt < 8; nt++) {
        uint32_t b0 = *(const uint32_t*)&ks[(nt * 8 + g) * 136 + cb];
        uint32_t b1 = *(const uint32_t*)&ks[(nt * 8 + g) * 136 + cb + 8];
        mma16816(sc[nt], a0, a1, a2, a3, b0, b1);
      }
    }

    // softmax (scores already scaled: Q pre-scaled in k1)
    float m0 = -1e30f, m1 = -1e30f;
#pragma unroll
    for (int nt = 0; nt < 8; nt++) {
      m0 = fmaxf(m0, fmaxf(sc[nt][0], sc[nt][1]));
      m1 = fmaxf(m1, fmaxf(sc[nt][2], sc[nt][3]));
    }
#pragma unroll
    for (int o = 1; o < 4; o <<= 1) {
      m0 = fmaxf(m0, __shfl_xor_sync(0xffffffffu, m0, o));
      m1 = fmaxf(m1, __shfl_xor_sync(0xffffffffu, m1, o));
    }
    float l0 = 0.f, l1 = 0.f;
#pragma unroll
    for (int nt = 0; nt < 8; nt++) {
      sc[nt][0] = __expf(sc[nt][0] - m0);
      sc[nt][1] = __expf(sc[nt][1] - m0);
      sc[nt][2] = __expf(sc[nt][2] - m1);
      sc[nt][3] = __expf(sc[nt][3] - m1);
      l0 += sc[nt][0] + sc[nt][1];
      l1 += sc[nt][2] + sc[nt][3];
    }
#pragma unroll
    for (int o = 1; o < 4; o <<= 1) {
      l0 += __shfl_xor_sync(0xffffffffu, l0, o);
      l1 += __shfl_xor_sync(0xffffffffu, l1, o);
    }
    float r0 = 1.f / l0, r1 = 1.f / l1;

    float oacc[4][4];
#pragma unroll
    for (int nv = 0; nv < 4; nv++)
#pragma unroll
      for (int q = 0; q < 4; q++) oacc[nv][q] = 0.f;
#pragma unroll
    for (int kt = 0; kt < 4; kt++) {
      uint32_t a0 = pack2(sc[2 * kt][0] * r0, sc[2 * kt][1] * r0);
      uint32_t a1 = pack2(sc[2 * kt][2] * r1, sc[2 * kt][3] * r1);
      uint32_t a2 = pack2(sc[2 * kt + 1][0] * r0, sc[2 * kt + 1][1] * r0);
      uint32_t a3 = pack2(sc[2 * kt + 1][2] * r1, sc[2 * kt + 1][3] * r1);
#pragma unroll
      for (int nv = 0; nv < 4; nv++) {
        int ch = h * 32 + nv * 8 + g;
        uint32_t b0 = *(const uint32_t*)&vs[ch * 72 + kt * 16 + 2 * tg];
        uint32_t b1 = *(const uint32_t*)&vs[ch * 72 + kt * 16 + 2 * tg + 8];
        mma16816(oacc[nv], a0, a1, a2, a3, b0, b1);
      }
    }
#pragma unroll
    for (int nv = 0; nv < 4; nv++) {
      int cc = h * 32 + nv * 8 + 2 * tg;
      *(uint32_t*)&os[(qr + g) * 136 + cc] = pack2(oacc[nv][0], oacc[nv][1]);
      *(uint32_t*)&os[(qr + g + 8) * 136 + cc] = pack2(oacc[nv][2], oacc[nv][3]);
    }
  }
  __syncthreads();

  __half* outp = g_attn + ((size_t)d * NWIN + win) * TOK * CHN;
  for (int j = tid; j < 1024; j += 128) {
    int tok = j >> 4, c8 = (j & 15) * 8;
    *(uint4*)&outp[tok * 128 + c8] = *(const uint4*)&os[tok * 136 + c8];
  }
}

// ===========================================================================
// K2b: projection GEMM. Tile = 2 windows (128 tok) x 128 out, K=128.
// Output NHWC fp16 (g_attp).
// ===========================================================================
struct K2bArgs { const float* pb[2]; };

__global__ __launch_bounds__(256, 2) void k2b_proj(K2bArgs a) {
  extern __shared__ char sm[];
  __half* Xs = (__half*)sm;        // [128][136]
  __half* Ws = Xs + 128 * 136;     // [128][136]

  int wp = blockIdx.x, d = blockIdx.y;
  int tid = threadIdx.x;
  const __half* src = g_attn + ((size_t)d * NWIN + (size_t)wp * 2) * TOK * CHN;
  for (int j = tid; j < 2048; j += 256) {
    int r = j >> 4, c8 = (j & 15) * 8;
    *(uint4*)&Xs[r * 136 + c8] = *(const uint4*)&src[r * 128 + c8];
  }
  const __half* Wg = g_wh + 98304 + d * 16384;
  for (int j = tid; j < 2048; j += 256) {
    int o = j >> 4, c8 = (j & 15) * 8;
    *(uint4*)&Ws[o * 136 + c8] = *(const uint4*)&Wg[o * 128 + c8];
  }
  __syncthreads();

  int warp = tid >> 5, lane = tid & 31;
  int g = lane >> 2, tg = lane & 3;
  int wm = warp >> 1, wn = warp & 1;

  float acc[2][8][4];
#pragma unroll
  for (int mt = 0; mt < 2; mt++)
#pragma unroll
    for (int nt = 0; nt < 8; nt++)
#pragma unroll
      for (int q = 0; q < 4; q++) acc[mt][nt][q] = 0.f;

#pragma unroll
  for (int kk = 0; kk < 8; kk++) {
    int cb = kk * 16 + 2 * tg;
    uint32_t af[2][4], bf[8][2];
#pragma unroll
    for (int mt = 0; mt < 2; mt++) {
      int r = wm * 32 + mt * 16;
      af[mt][0] = *(const uint32_t*)&Xs[(r + g) * 136 + cb];
      af[mt][1] = *(const uint32_t*)&Xs[(r + g + 8) * 136 + cb];
      af[mt][2] = *(const uint32_t*)&Xs[(r + g) * 136 + cb + 8];
      af[mt][3] = *(const uint32_t*)&Xs[(r + g + 8) * 136 + cb + 8];
    }
#pragma unroll
    for (int nt = 0; nt < 8; nt++) {
      int o = wn * 64 + nt * 8 + g;
      bf[nt][0] = *(const uint32_t*)&Ws[o * 136 + cb];
      bf[nt][1] = *(const uint32_t*)&Ws[o * 136 + cb + 8];
    }
#pragma unroll
    for (int mt = 0; mt < 2; mt++)
#pragma unroll
      for (int nt = 0; nt < 8; nt++)
        mma16816(acc[mt][nt], af[mt][0], af[mt][1], af[mt][2], af[mt][3],
                 bf[nt][0], bf[nt][1]);
  }
  __syncthreads();

  const float* pb = a.pb[d];
#pragma unroll
  for (int mt = 0; mt < 2; mt++) {
    int tok = wm * 32 + mt * 16 + g;
#pragma unroll
    for (int nt = 0; nt < 8; nt++) {
      int o = wn * 64 + nt * 8 + 2 * tg;
      *(uint32_t*)&Xs[tok * 136 + o] =
          pack2(acc[mt][nt][0] + pb[o], acc[mt][nt][1] + pb[o + 1]);
      *(uint32_t*)&Xs[(tok + 8) * 136 + o] =
          pack2(acc[mt][nt][2] + pb[o], acc[mt][nt][3] + pb[o + 1]);
    }
  }
  __syncthreads();

  __half* outp = g_attp + (size_t)d * BCHW;
  for (int j = tid; j < 2048; j += 256) {
    int tok = j >> 4, c8 = (j & 15) * 8;
    int win = wp * 2 + (tok >> 6);
    int t = tok & 63;
    int b = win >> 10, wy = (win >> 5) & 31, wx = win & 31;
    int hw = wy * 2048 + wx * 8 + (t >> 3) * 256 + (t & 7);
    *(uint4*)&outp[((size_t)b * HWSZ + hw) * 128 + c8] =
        *(const uint4*)&Xs[tok * 136 + c8];
  }
}

// ===========================================================================
// K3a: gate GEMM (K=256, two halves) + sigma out + residual -> g_new.
// z=0: opt, z=1: sar. Tile 128px x 128out.
// ===========================================================================
struct K3aArgs { const float* gb[2]; float* out; };

__global__ __launch_bounds__(256, 2) void k3a_gate(K3aArgs a) {
  extern __shared__ char sm[];
  __half* Xf = (__half*)sm;         // [128][136] F fp16
  __half* Xa = Xf + 128 * 136;      // [128][136] att fp16
  __half* Ws = Xa + 128 * 136;      // [128][136] weights (half-K at a time) / stage

  int tile = blockIdx.x, z = blockIdx.y;
  int p0 = tile * 128;
  int b = p0 >> 16;
  int hw0 = p0 & 65535;
  int tid = threadIdx.x;

  const __half* Fsrc = g_Fh + (size_t)z * BCHW + ((size_t)b * HWSZ + hw0) * 128;
  const __half* Asrc = g_attp + (size_t)z * BCHW + ((size_t)b * HWSZ + hw0) * 128;
  for (int j = tid; j < 2048; j += 256) {
    int px = j >> 4, c8 = (j & 15) * 8;
    *(uint4*)&Xf[px * 136 + c8] = *(const uint4*)&Fsrc[(size_t)px * 128 + c8];
    *(uint4*)&Xa[px * 136 + c8] = *(const uint4*)&Asrc[(size_t)px * 128 + c8];
  }

  int gbase = 131072 + z * 32768;
  int warp = tid >> 5, lane = tid & 31;
  int g = lane >> 2, tg = lane & 3;
  int wm = warp >> 1, wn = warp & 1;

  float acc[2][8][4];
#pragma unroll
  for (int mt = 0; mt < 2; mt++)
#pragma unroll
    for (int nt = 0; nt < 8; nt++)
#pragma unroll
      for (int q = 0; q < 4; q++) acc[mt][nt][q] = 0.f;

  for (int half = 0; half < 2; half++) {
    __syncthreads();
    for (int j = tid; j < 2048; j += 256) {
      int o = j >> 4, c8 = (j & 15) * 8;
      *(uint4*)&Ws[o * 136 + c8] = *(const uint4*)&g_wh[gbase + o * 256 + half * 128 + c8];
    }
    __syncthreads();
    const __half* A = half == 0 ? Xf : Xa;
#pragma unroll
    for (int kk = 0; kk < 8; kk++) {
      int cb = kk * 16 + 2 * tg;
      uint32_t af[2][4], bf[8][2];
#pragma unroll
      for (int mt = 0; mt < 2; mt++) {
        int r = wm * 32 + mt * 16;
        af[mt][0] = *(const uint32_t*)&A[(r + g) * 136 + cb];
        af[mt][1] = *(const uint32_t*)&A[(r + g + 8) * 136 + cb];
        af[mt][2] = *(const uint32_t*)&A[(r + g) * 136 + cb + 8];
        af[mt][3] = *(const uint32_t*)&A[(r + g + 8) * 136 + cb + 8];
      }
#pragma unroll
      for (int nt = 0; nt < 8; nt++) {
        int o = wn * 64 + nt * 8 + g;
        bf[nt][0] = *(const uint32_t*)&Ws[o * 136 + cb];
        bf[nt][1] = *(const uint32_t*)&Ws[o * 136 + cb + 8];
      }
#pragma unroll
      for (int mt = 0; mt < 2; mt++)
#pragma unroll
        for (int nt = 0; nt < 8; nt++)
          mma16816(acc[mt][nt], af[mt][0], af[mt][1], af[mt][2], af[mt][3],
                   bf[nt][0], bf[nt][1]);
    }
  }

  // epilogue: sigma (direct f32, full 32B sectors) + new = F + sigma*att (regs)
  const float* gb = a.gb[z];
  float* sig = a.out + (size_t)(1 + z) * BCHW + (size_t)b * CHN * HWSZ + hw0;
  uint32_t nw[2][8][2];
#pragma unroll
  for (int mt = 0; mt < 2; mt++) {
    int px = wm * 32 + mt * 16 + g;
#pragma unroll
    for (int nt = 0; nt < 8; nt++) {
      int o = wn * 64 + nt * 8 + 2 * tg;
      float s0 = 1.f / (1.f + __expf(-(acc[mt][nt][0] + gb[o])));
      float s1 = 1.f / (1.f + __expf(-(acc[mt][nt][1] + gb[o + 1])));
      float s2 = 1.f / (1.f + __expf(-(acc[mt][nt][2] + gb[o])));
      float s3 = 1.f / (1.f + __expf(-(acc[mt][nt][3] + gb[o + 1])));
      sig[(size_t)o * HWSZ + px] = s0;
      sig[(size_t)(o + 1) * HWSZ + px] = s1;
      sig[(size_t)o * HWSZ + px + 8] = s2;
      sig[(size_t)(o + 1) * HWSZ + px + 8] = s3;
      __half2 f0 = *(const __half2*)&Xf[px * 136 + o];
      __half2 f1 = *(const __half2*)&Xf[(px + 8) * 136 + o];
      __half2 a0 = *(const __half2*)&Xa[px * 136 + o];
      __half2 a1 = *(const __half2*)&Xa[(px + 8) * 136 + o];
      nw[mt][nt][0] = pack2(__half2float(f0.x) + s0 * __half2float(a0.x),
                            __half2float(f0.y) + s1 * __half2float(a0.y));
      nw[mt][nt][1] = pack2(__half2float(f1.x) + s2 * __half2float(a1.x),
                            __half2float(f1.y) + s3 * __half2float(a1.y));
    }
  }
  __syncthreads();
#pragma unroll
  for (int mt = 0; mt < 2; mt++) {
    int px = wm * 32 + mt * 16 + g;
#pragma unroll
    for (int nt = 0; nt < 8; nt++) {
      int o = wn * 64 + nt * 8 + 2 * tg;
      *(uint32_t*)&Ws[px * 136 + o] = nw[mt][nt][0];
      *(uint32_t*)&Ws[(px + 8) * 136 + o] = nw[mt][nt][1];
    }
  }
  __syncthreads();
  __half* outp = g_new + (size_t)z * BCHW + ((size_t)b * HWSZ + hw0) * 128;
  for (int j = tid; j < 2048; j += 256) {
    int px = j >> 4, c8 = (j & 15) * 8;
    *(uint4*)&outp[(size_t)px * 128 + c8] = *(const uint4*)&Ws[px * 136 + c8];
  }
}

// ===========================================================================
// K3b: fuse GEMM K=256 + BN + SiLU -> d_out f32 (direct sector-complete).
// ===========================================================================
struct K3bArgs {
  const float *fb, *gamma, *beta, *mean, *var;
  float* out;
};

__global__ __launch_bounds__(256, 2) void k3b_fuse(K3bArgs a) {
  extern __shared__ char sm[];
  __half* Xs = (__half*)sm;          // [128][264]
  __half* Ws = Xs + 128 * 264;       // [128][136]

  int tile = blockIdx.x;
  int p0 = tile * 128;
  int b = p0 >> 16;
  int hw0 = p0 & 65535;
  int tid = threadIdx.x;

  for (int j = tid; j < 4096; j += 256) {
    int px = j >> 5, c8 = (j & 31) * 8;
    const __half* src = (c8 < 128)
        ? g_new + ((size_t)b * HWSZ + hw0 + px) * 128 + c8
        : g_new + BCHW + ((size_t)b * HWSZ + hw0 + px) * 128 + (c8 - 128);
    *(uint4*)&Xs[px * 264 + c8] = *(const uint4*)src;
  }

  int warp = tid >> 5, lane = tid & 31;
  int g = lane >> 2, tg = lane & 3;
  int wm = warp >> 1, wn = warp & 1;

  float acc[2][8][4];
#pragma unroll
  for (int mt = 0; mt < 2; mt++)
#pragma unroll
    for (int nt = 0; nt < 8; nt++)
#pragma unroll
      for (int q = 0; q < 4; q++) acc[mt][nt][q] = 0.f;

  for (int half = 0; half < 2; half++) {
    __syncthreads();
    for (int j = tid; j < 2048; j += 256) {
      int o = j >> 4, c8 = (j & 15) * 8;
      *(uint4*)&Ws[o * 136 + c8] = *(const uint4*)&g_wh[196608 + o * 256 + half * 128 + c8];
    }
    __syncthreads();
#pragma unroll
    for (int kk = 0; kk < 8; kk++) {
      int cbA = half * 128 + kk * 16 + 2 * tg;
      int cbB = kk * 16 + 2 * tg;
      uint32_t af[2][4], bf[8][2];
#pragma unroll
      for (int mt = 0; mt < 2; mt++) {
        int r = wm * 32 + mt * 16;
        af[mt][0] = *(const uint32_t*)&Xs[(r + g) * 264 + cbA];
        af[mt][1] = *(const uint32_t*)&Xs[(r + g + 8) * 264 + cbA];
        af[mt][2] = *(const uint32_t*)&Xs[(r + g) * 264 + cbA + 8];
        af[mt][3] = *(const uint32_t*)&Xs[(r + g + 8) * 264 + cbA + 8];
      }
#pragma unroll
      for (int nt = 0; nt < 8; nt++) {
        int o = wn * 64 + nt * 8 + g;
        bf[nt][0] = *(const uint32_t*)&Ws[o * 136 + cbB];
        bf[nt][1] = *(const uint32_t*)&Ws[o * 136 + cbB + 8];
      }
#pragma unroll
      for (int mt = 0; mt < 2; mt++)
#pragma unroll
        for (int nt = 0; nt < 8; nt++)
          mma16816(acc[mt][nt], af[mt][0], af[mt][1], af[mt][2], af[mt][3],
                   bf[nt][0], bf[nt][1]);
    }
  }

  float* outp = a.out + (size_t)b * CHN * HWSZ + hw0;
#pragma unroll
  for (int mt = 0; mt < 2; mt++) {
    int px = wm * 32 + mt * 16 + g;
#pragma unroll
    for (int nt = 0; nt < 8; nt++) {
      int o = wn * 64 + nt * 8 + 2 * tg;
      float inv0 = a.gamma[o] * rsqrtf(a.var[o] + 1e-5f);
      float inv1 = a.gamma[o + 1] * rsqrtf(a.var[o + 1] + 1e-5f);
      float sh0 = a.beta[o] - a.mean[o] * inv0;
      float sh1 = a.beta[o + 1] - a.mean[o + 1] * inv1;
#pragma unroll
      for (int q = 0; q < 4; q++) {
        float v = acc[mt][nt][q] + ((q & 1) ? a.fb[o + 1] : a.fb[o]);
        float f = v * ((q & 1) ? inv1 : inv0) + ((q & 1) ? sh1 : sh0);
        float r = f / (1.f + __expf(-f));
        int oo = (q & 1) ? o + 1 : o;
        int pp = px + ((q >> 1) ? 8 : 0);
        outp[(size_t)oo * HWSZ + pp] = r;
      }
    }
  }
}

// ===========================================================================
extern "C" void kernel_launch(void* const* d_in, const int* in_sizes, int n_in,
                              void* d_out, int out_size) {
  const float* F_opt = (const float*)d_in[0];
  const float* F_sar = (const float*)d_in[1];

  cudaFuncSetAttribute(k1_qkv, cudaFuncAttributeMaxDynamicSharedMemorySize, 69632);
  cudaFuncSetAttribute(k2_attn, cudaFuncAttributeMaxDynamicSharedMemorySize, 70656);
  cudaFuncSetAttribute(k2b_proj, cudaFuncAttributeMaxDynamicSharedMemorySize, 69632);
  cudaFuncSetAttribute(k3a_gate, cudaFuncAttributeMaxDynamicSharedMemorySize, 104448);
  cudaFuncSetAttribute(k3b_fuse, cudaFuncAttributeMaxDynamicSharedMemorySize, 102400);

  PrepArgs pa;
  pa.w[0] = (const float*)d_in[2];
  pa.w[1] = (const float*)d_in[4];
  pa.w[2] = (const float*)d_in[6];
  pa.w[3] = (const float*)d_in[8];
  pa.w[4] = (const float*)d_in[10];
  pa.w[5] = (const float*)d_in[12];
  pa.w[6] = (const float*)d_in[14];
  pa.w[7] = (const float*)d_in[16];
  pa.w[8] = (const float*)d_in[18];
  pa.w[9] = (const float*)d_in[20];
  pa.w[10] = (const float*)d_in[22];
  k0_prep<<<896, 256>>>(pa);

  K1Args a1;
  a1.x[0] = F_opt; a1.x[1] = F_sar;
  a1.bi[0] = (const float*)d_in[3];
  a1.bi[1] = (const float*)d_in[5];
  a1.bi[2] = (const float*)d_in[7];
  a1.bi[3] = (const float*)d_in[9];
  a1.bi[4] = (const float*)d_in[11];
  a1.bi[5] = (const float*)d_in[13];
  k1_qkv<<<dim3(2048, 2), 256, 69632>>>(a1);

  k2_attn<<<dim3(4096, 2), 128, 70656>>>();

  K2bArgs a2b;
  a2b.pb[0] = (const float*)d_in[15];
  a2b.pb[1] = (const float*)d_in[17];
  k2b_proj<<<dim3(2048, 2), 256, 69632>>>(a2b);

  K3aArgs a3a;
  a3a.gb[0] = (const float*)d_in[19];
  a3a.gb[1] = (const float*)d_in[21];
  a3a.out = (float*)d_out;
  k3a_gate<<<dim3(2048, 2), 256, 104448>>>(a3a);

  K3bArgs a3b;
  a3b.fb = (const float*)d_in[23];
  a3b.gamma = (const float*)d_in[24];
  a3b.beta = (const float*)d_in[25];
  a3b.mean = (const float*)d_in[26];
  a3b.var = (const float*)d_in[27];
  a3b.out = (float*)d_out;
  k3b_fuse<<<2048, 256, 102400>>>(a3b);
}